// round 1
// baseline (speedup 1.0000x reference)
#include <cuda_runtime.h>
#include <cuda_bf16.h>

#define NN 50000
#define EMAX 800000
#define ETOT (EMAX + NN)
#define IN_CH 128
#define HID 64
#define HEADS 4
#define D1 (HEADS * HID)   // 256

// ---------------- scratch (static device globals; no runtime alloc) --------
__device__ __align__(128) float g_h1[NN * D1];     // x @ W1
__device__ __align__(128) float g_buf1[NN * D1];   // elu(agg1 + b1)
__device__ __align__(128) float g_h2[NN * HID];    // buf1 @ W2
__device__ __align__(128) float g_buf2[NN * HID];  // elu(agg2 + b2)
__device__ __align__(128) float g_asrc1[NN * HEADS];
__device__ __align__(128) float g_adst1[NN * HEADS];
__device__ __align__(128) float g_asrc2[NN];
__device__ __align__(128) float g_adst2[NN];
__device__ __align__(128) int   g_deg[NN];
__device__ __align__(128) int   g_rowptr[NN + 1];
__device__ __align__(128) int   g_cursor[NN];
__device__ __align__(128) int   g_esrc[ETOT];

// ---------------- CSR build -------------------------------------------------
__global__ void k_zero_deg() {
    int i = blockIdx.x * blockDim.x + threadIdx.x;
    if (i < NN) g_deg[i] = 0;
}

__global__ void k_count(const int* __restrict__ dst, int E) {
    int i = blockIdx.x * blockDim.x + threadIdx.x;
    if (i < E) atomicAdd(&g_deg[dst[i]], 1);
}

// single-block scan: rowptr[i+1] = prefix(deg[i] + 1)   (+1 = self loop)
__global__ void k_scan() {
    __shared__ int warp_sums[32];
    __shared__ int s_carry;
    int t = threadIdx.x;
    if (t == 0) { s_carry = 0; g_rowptr[0] = 0; }
    __syncthreads();
    for (int base = 0; base < NN; base += 1024) {
        int i = base + t;
        int v = (i < NN) ? (g_deg[i] + 1) : 0;
        int x = v;
        #pragma unroll
        for (int o = 1; o < 32; o <<= 1) {
            int y = __shfl_up_sync(0xFFFFFFFF, x, o);
            if ((t & 31) >= o) x += y;
        }
        if ((t & 31) == 31) warp_sums[t >> 5] = x;
        __syncthreads();
        if (t < 32) {
            int ws = warp_sums[t];
            #pragma unroll
            for (int o = 1; o < 32; o <<= 1) {
                int y = __shfl_up_sync(0xFFFFFFFF, ws, o);
                if (t >= o) ws += y;
            }
            warp_sums[t] = ws;
        }
        __syncthreads();
        int incl = x + ((t >= 32) ? warp_sums[(t >> 5) - 1] : 0) + s_carry;
        if (i < NN) { g_rowptr[i + 1] = incl; g_cursor[i] = incl - v; }
        __syncthreads();
        if (t == 1023) s_carry = incl;
        __syncthreads();
    }
}

__global__ void k_scatter(const int* __restrict__ src, const int* __restrict__ dst, int E) {
    int i = blockIdx.x * blockDim.x + threadIdx.x;
    if (i < E) {
        int p = atomicAdd(&g_cursor[dst[i]], 1);
        g_esrc[p] = src[i];
    } else if (i < E + NN) {
        int n = i - E;              // self loop
        int p = atomicAdd(&g_cursor[n], 1);
        g_esrc[p] = n;
    }
}

// ---------------- fp32 tiled GEMM: C[M,N] = A[M,K] @ B[K,N] ----------------
// BM=BN=64, BK=16, 256 threads, 4x4 per thread. K%16==0, N%64==0 assumed.
__global__ void k_gemm(const float* __restrict__ A, const float* __restrict__ B,
                       float* __restrict__ C, int M, int N, int K) {
    __shared__ float As[16][65];
    __shared__ float Bs[16][64];
    int t = threadIdx.x;
    int tx = t & 15, ty = t >> 4;
    int row0 = blockIdx.y * 64;
    int col0 = blockIdx.x * 64;
    int am = t >> 2;
    int ak = (t & 3) * 4;
    int bk = t >> 4;
    int bn = (t & 15) * 4;
    float acc[4][4];
    #pragma unroll
    for (int i = 0; i < 4; i++)
        #pragma unroll
        for (int j = 0; j < 4; j++) acc[i][j] = 0.f;

    for (int k0 = 0; k0 < K; k0 += 16) {
        float4 av = make_float4(0.f, 0.f, 0.f, 0.f);
        int arow = row0 + am;
        if (arow < M)
            av = *reinterpret_cast<const float4*>(A + (size_t)arow * K + k0 + ak);
        As[ak + 0][am] = av.x; As[ak + 1][am] = av.y;
        As[ak + 2][am] = av.z; As[ak + 3][am] = av.w;
        float4 bv = *reinterpret_cast<const float4*>(B + (size_t)(k0 + bk) * N + col0 + bn);
        *reinterpret_cast<float4*>(&Bs[bk][bn]) = bv;
        __syncthreads();
        #pragma unroll
        for (int k = 0; k < 16; k++) {
            float a[4], b[4];
            #pragma unroll
            for (int i = 0; i < 4; i++) a[i] = As[k][ty * 4 + i];
            #pragma unroll
            for (int j = 0; j < 4; j++) b[j] = Bs[k][tx * 4 + j];
            #pragma unroll
            for (int i = 0; i < 4; i++)
                #pragma unroll
                for (int j = 0; j < 4; j++) acc[i][j] += a[i] * b[j];
        }
        __syncthreads();
    }
    #pragma unroll
    for (int i = 0; i < 4; i++) {
        int row = row0 + ty * 4 + i;
        if (row < M) {
            #pragma unroll
            for (int j = 0; j < 4; j++)
                C[(size_t)row * N + col0 + tx * 4 + j] = acc[i][j];
        }
    }
}

// ---------------- attention scores -----------------------------------------
// layer 1: block = 128 threads (4 warps), one node per block, warp h -> head h
__global__ void k_scores1(const float* __restrict__ att_src, const float* __restrict__ att_dst) {
    int n = blockIdx.x;
    int t = threadIdx.x;
    int h = t >> 5, lane = t & 31;
    const float* hp = g_h1 + (size_t)n * D1 + h * HID;
    float s1 = hp[lane] * att_src[h * HID + lane] + hp[lane + 32] * att_src[h * HID + lane + 32];
    float s2 = hp[lane] * att_dst[h * HID + lane] + hp[lane + 32] * att_dst[h * HID + lane + 32];
    #pragma unroll
    for (int o = 16; o; o >>= 1) {
        s1 += __shfl_down_sync(0xFFFFFFFF, s1, o);
        s2 += __shfl_down_sync(0xFFFFFFFF, s2, o);
    }
    if (lane == 0) {
        g_asrc1[n * HEADS + h] = s1;
        g_adst1[n * HEADS + h] = s2;
    }
}

// layer 2: block = 256 threads = 8 warps, one node per warp
__global__ void k_scores2(const float* __restrict__ att_src, const float* __restrict__ att_dst) {
    int w = threadIdx.x >> 5, lane = threadIdx.x & 31;
    int n = blockIdx.x * 8 + w;
    if (n >= NN) return;
    const float* hp = g_h2 + (size_t)n * HID;
    float s1 = hp[lane] * att_src[lane] + hp[lane + 32] * att_src[lane + 32];
    float s2 = hp[lane] * att_dst[lane] + hp[lane + 32] * att_dst[lane + 32];
    #pragma unroll
    for (int o = 16; o; o >>= 1) {
        s1 += __shfl_down_sync(0xFFFFFFFF, s1, o);
        s2 += __shfl_down_sync(0xFFFFFFFF, s2, o);
    }
    if (lane == 0) {
        g_asrc2[n] = s1;
        g_adst2[n] = s2;
    }
}

// ---------------- aggregation (softmax over incoming edges + gather) --------
__device__ __forceinline__ float lrelu(float x) { return x > 0.f ? x : 0.2f * x; }

// layer 1: one node per 256-thread block; tid = h*64 + c
__global__ void k_agg1(const float* __restrict__ bias) {
    int n = blockIdx.x;
    int tid = threadIdx.x;
    int h = tid >> 6;
    __shared__ float sm[HEADS], sinv[HEADS];
    int beg = g_rowptr[n], end = g_rowptr[n + 1];
    if (tid < HEADS) {
        float adh = g_adst1[n * HEADS + tid];
        float m = -1e30f, d = 0.f;
        for (int e = beg; e < end; e++) {
            int s = g_esrc[e];
            float x = lrelu(g_asrc1[s * HEADS + tid] + adh);
            float mn = fmaxf(m, x);
            d = d * __expf(m - mn) + __expf(x - mn);
            m = mn;
        }
        sm[tid] = m;
        sinv[tid] = 1.f / (d + 1e-16f);
    }
    __syncthreads();
    float m = sm[h], inv = sinv[h];
    float ad = g_adst1[n * HEADS + h];
    float acc = 0.f;
    for (int e = beg; e < end; e++) {
        int s = g_esrc[e];
        float x = lrelu(g_asrc1[s * HEADS + h] + ad);
        float w = __expf(x - m) * inv;
        acc += g_h1[(size_t)s * D1 + tid] * w;
    }
    float v = acc + bias[tid];
    g_buf1[(size_t)n * D1 + tid] = v > 0.f ? v : __expf(v) - 1.f;   // elu
}

// layer 2: one node per 64-thread block, single head
__global__ void k_agg2(const float* __restrict__ bias) {
    int n = blockIdx.x;
    int tid = threadIdx.x;
    __shared__ float sm, sinv;
    int beg = g_rowptr[n], end = g_rowptr[n + 1];
    float ad = g_adst2[n];
    if (tid == 0) {
        float m = -1e30f, d = 0.f;
        for (int e = beg; e < end; e++) {
            int s = g_esrc[e];
            float x = lrelu(g_asrc2[s] + ad);
            float mn = fmaxf(m, x);
            d = d * __expf(m - mn) + __expf(x - mn);
            m = mn;
        }
        sm = m;
        sinv = 1.f / (d + 1e-16f);
    }
    __syncthreads();
    float m = sm, inv = sinv;
    float acc = 0.f;
    for (int e = beg; e < end; e++) {
        int s = g_esrc[e];
        float x = lrelu(g_asrc2[s] + ad);
        acc += g_h2[(size_t)s * HID + tid] * (__expf(x - m) * inv);
    }
    float v = acc + bias[tid];
    g_buf2[(size_t)n * HID + tid] = v > 0.f ? v : __expf(v) - 1.f;  // elu
}

// ---------------- fused MLP head: relu(h@Wm1+bm1)@Wm2+bm2 ------------------
// block = 256 threads = 8 nodes x 32 hidden
__global__ void k_mlp(const float* __restrict__ Wm1, const float* __restrict__ bm1,
                      const float* __restrict__ Wm2, const float* __restrict__ bm2,
                      float* __restrict__ out) {
    __shared__ float sW1[HID * 32];
    __shared__ float sW2[32 * 2];
    __shared__ float sb1[32], sb2[2];
    __shared__ float hm[8][33];
    int t = threadIdx.x;
    for (int i = t; i < HID * 32; i += 256) sW1[i] = Wm1[i];
    if (t < 64) sW2[t] = Wm2[t];
    if (t < 32) sb1[t] = bm1[t];
    if (t < 2)  sb2[t] = bm2[t];
    __syncthreads();
    int nl = t >> 5, j = t & 31;
    int node = blockIdx.x * 8 + nl;
    if (node < NN) {
        const float* hrow = g_buf2 + (size_t)node * HID;
        float acc = sb1[j];
        #pragma unroll
        for (int k = 0; k < HID; k++) acc += hrow[k] * sW1[k * 32 + j];
        hm[nl][j] = fmaxf(acc, 0.f);
    }
    __syncthreads();
    if (node < NN && j < 2) {
        float acc = sb2[j];
        #pragma unroll
        for (int k = 0; k < 32; k++) acc += hm[nl][k] * sW2[k * 2 + j];
        out[node * 2 + j] = acc;
    }
}

// ---------------- launch ----------------------------------------------------
extern "C" void kernel_launch(void* const* d_in, const int* in_sizes, int n_in,
                              void* d_out, int out_size) {
    const float* x        = (const float*)d_in[0];
    const int*   eidx     = (const int*)d_in[1];
    const float* W1       = (const float*)d_in[2];
    const float* att_src1 = (const float*)d_in[3];
    const float* att_dst1 = (const float*)d_in[4];
    const float* b1       = (const float*)d_in[5];
    const float* W2       = (const float*)d_in[6];
    const float* att_src2 = (const float*)d_in[7];
    const float* att_dst2 = (const float*)d_in[8];
    const float* b2       = (const float*)d_in[9];
    const float* Wm1      = (const float*)d_in[10];
    const float* bm1      = (const float*)d_in[11];
    const float* Wm2      = (const float*)d_in[12];
    const float* bm2      = (const float*)d_in[13];
    float* out = (float*)d_out;

    int E = in_sizes[1] / 2;
    const int* srcp = eidx;
    const int* dstp = eidx + E;

    float *h1p, *buf1p, *h2p;
    cudaGetSymbolAddress((void**)&h1p,  g_h1);
    cudaGetSymbolAddress((void**)&buf1p, g_buf1);
    cudaGetSymbolAddress((void**)&h2p,  g_h2);

    // CSR build (dst-grouped, with self loops)
    k_zero_deg<<<(NN + 255) / 256, 256>>>();
    k_count<<<(E + 255) / 256, 256>>>(dstp, E);
    k_scan<<<1, 1024>>>();
    k_scatter<<<(E + NN + 255) / 256, 256>>>(srcp, dstp, E);

    // layer 1
    k_gemm<<<dim3(D1 / 64, (NN + 63) / 64), 256>>>(x, W1, h1p, NN, D1, IN_CH);
    k_scores1<<<NN, 128>>>(att_src1, att_dst1);
    k_agg1<<<NN, 256>>>(b1);

    // layer 2
    k_gemm<<<dim3(HID / 64, (NN + 63) / 64), 256>>>(buf1p, W2, h2p, NN, HID, D1);
    k_scores2<<<(NN + 7) / 8, 256>>>(att_src2, att_dst2);
    k_agg2<<<NN, 64>>>(b2);

    // MLP head
    k_mlp<<<(NN + 7) / 8, 256>>>(Wm1, bm1, Wm2, bm2, out);
}

// round 2
// speedup vs baseline: 1.7079x; 1.7079x over previous
#include <cuda_runtime.h>
#include <cuda_bf16.h>
#include <cstdint>

#define NN 50000
#define EMAX 800000
#define ETOT (EMAX + NN)
#define IN_CH 128
#define HID 64
#define HEADS 4
#define D1 (HEADS * HID)   // 256
#define NBLK 49            // ceil(NN/1024)

// ---------------- scratch (static device globals; no runtime alloc) --------
__device__ __align__(128) float g_h1[NN * D1];     // x @ W1
__device__ __align__(128) float g_buf1[NN * D1];   // elu(agg1 + b1)
__device__ __align__(128) float g_h2[NN * HID];    // buf1 @ W2
__device__ __align__(128) float g_buf2[NN * HID];  // elu(agg2 + b2)
__device__ __align__(128) float g_asrc1[NN * HEADS];
__device__ __align__(128) float g_adst1[NN * HEADS];
__device__ __align__(128) float g_asrc2[NN];
__device__ __align__(128) float g_adst2[NN];
__device__ __align__(128) float g_esc[(size_t)HEADS * ETOT];  // per-edge scores scratch
__device__ __align__(128) int   g_deg[NN];
__device__ __align__(128) int   g_rowptr[NN + 1];
__device__ __align__(128) int   g_cursor[NN];
__device__ __align__(128) int   g_esrc[ETOT];
__device__ __align__(128) int   g_part[64];

// ---------------- CSR build -------------------------------------------------
__global__ void k_zero_deg() {
    int i = blockIdx.x * blockDim.x + threadIdx.x;
    if (i < NN) g_deg[i] = 0;
}

__global__ void k_count(const int* __restrict__ dst, int E) {
    int i = blockIdx.x * blockDim.x + threadIdx.x;
    if (i < E) atomicAdd(&g_deg[dst[i]], 1);
}

// two-level scan: rowptr[i+1] = prefix(deg[i] + 1)  (+1 = self loop)
__global__ void k_scan1() {
    __shared__ int ws[32];
    int t = threadIdx.x;
    int i = blockIdx.x * 1024 + t;
    int v = (i < NN) ? (g_deg[i] + 1) : 0;
    int x = v;
    #pragma unroll
    for (int o = 1; o < 32; o <<= 1) {
        int y = __shfl_up_sync(0xFFFFFFFF, x, o);
        if ((t & 31) >= o) x += y;
    }
    if ((t & 31) == 31) ws[t >> 5] = x;
    __syncthreads();
    if (t < 32) {
        int s = ws[t];
        #pragma unroll
        for (int o = 1; o < 32; o <<= 1) {
            int y = __shfl_up_sync(0xFFFFFFFF, s, o);
            if (t >= o) s += y;
        }
        ws[t] = s;
    }
    __syncthreads();
    int incl = x + ((t >= 32) ? ws[(t >> 5) - 1] : 0);
    if (i < NN) g_rowptr[i + 1] = incl;
    if (t == 1023) g_part[blockIdx.x] = incl;
}

__global__ void k_scan2() {   // 32 threads, scans NBLK (<=64) partials -> exclusive
    int l = threadIdx.x;
    int a = (l < NBLK) ? g_part[l] : 0;
    int b = (l + 32 < NBLK) ? g_part[l + 32] : 0;
    int ia = a;
    #pragma unroll
    for (int o = 1; o < 32; o <<= 1) {
        int y = __shfl_up_sync(0xFFFFFFFF, ia, o);
        if (l >= o) ia += y;
    }
    int tot = __shfl_sync(0xFFFFFFFF, ia, 31);
    int ib = b;
    #pragma unroll
    for (int o = 1; o < 32; o <<= 1) {
        int y = __shfl_up_sync(0xFFFFFFFF, ib, o);
        if (l >= o) ib += y;
    }
    g_part[l] = ia - a;
    g_part[l + 32] = tot + ib - b;
}

__global__ void k_scan3() {
    int i = blockIdx.x * blockDim.x + threadIdx.x;
    if (i >= NN) return;
    int off = g_part[i >> 10];
    int rp = g_rowptr[i + 1] + off;
    g_rowptr[i + 1] = rp;
    g_cursor[i] = rp - (g_deg[i] + 1);
    if (i == 0) g_rowptr[0] = 0;
}

__global__ void k_scatter(const int* __restrict__ src, const int* __restrict__ dst, int E) {
    int i = blockIdx.x * blockDim.x + threadIdx.x;
    if (i < E) {
        int p = atomicAdd(&g_cursor[dst[i]], 1);
        g_esrc[p] = src[i];
    } else if (i < E + NN) {
        int n = i - E;              // self loop
        int p = atomicAdd(&g_cursor[n], 1);
        g_esrc[p] = n;
    }
}

// ---------------- fp32 GEMM, BM=128 BN=64 BK=16, cp.async double-buffered --
__device__ __forceinline__ void cp16(uint32_t dst, const void* src, int sz) {
    asm volatile("cp.async.ca.shared.global [%0], [%1], 16, %2;\n"
                 :: "r"(dst), "l"(src), "r"(sz));
}

__global__ __launch_bounds__(256) void k_gemm(
        const float* __restrict__ A, const float* __restrict__ B,
        float* __restrict__ C, int M, int N, int K) {
    __shared__ float As[2][128][20];   // row-major tile, 20-float row stride (16B aligned)
    __shared__ float Bs[2][16][64];
    int t = threadIdx.x;
    int tx = t & 15, ty = t >> 4;
    int row0 = blockIdx.y * 128, col0 = blockIdx.x * 64;

    uint32_t sA = (uint32_t)__cvta_generic_to_shared(&As[0][0][0]);
    uint32_t sB = (uint32_t)__cvta_generic_to_shared(&Bs[0][0][0]);

    // A loads: thread t -> row t>>1, quads at k4 = (t&1)*8 + {0,4}
    int arow = row0 + (t >> 1);
    const float* Abase = A + (size_t)arow * K + ((t & 1) << 3);
    int asz = (arow < M) ? 16 : 0;
    uint32_t sAoff = sA + ((((t >> 1) * 20) + ((t & 1) << 3)) << 2);
    // B loads: thread t -> k row t>>4, cols (t&15)*4
    int brow = t >> 4, bc = (t & 15) << 2;
    const float* Bbase = B + (size_t)brow * N + col0 + bc;
    uint32_t sBoff = sB + (((brow << 6) + bc) << 2);

    float acc[8][4];
    #pragma unroll
    for (int i = 0; i < 8; i++)
        #pragma unroll
        for (int j = 0; j < 4; j++) acc[i][j] = 0.f;

    const uint32_t ABUF = 128 * 20 * 4;
    const uint32_t BBUF = 16 * 64 * 4;
    int nIter = K >> 4;

    // prologue: stage k-tile 0 into buf 0
    cp16(sAoff, Abase, asz);
    cp16(sAoff + 16, Abase + 4, asz);
    cp16(sBoff, Bbase, 16);
    asm volatile("cp.async.commit_group;\n" ::: "memory");

    for (int it = 0; it < nIter; it++) {
        int buf = it & 1;
        if (it + 1 < nIter) {
            int k0 = (it + 1) << 4;
            uint32_t bo = (buf ^ 1) ? ABUF : 0u;
            uint32_t bb = (buf ^ 1) ? BBUF : 0u;
            cp16(sAoff + bo, Abase + k0, asz);
            cp16(sAoff + bo + 16, Abase + k0 + 4, asz);
            cp16(sBoff + bb, Bbase + (size_t)k0 * N, 16);
            asm volatile("cp.async.commit_group;\n" ::: "memory");
            asm volatile("cp.async.wait_group 1;\n" ::: "memory");
        } else {
            asm volatile("cp.async.wait_group 0;\n" ::: "memory");
        }
        __syncthreads();
        #pragma unroll
        for (int k = 0; k < 16; k++) {
            float4 b4 = *reinterpret_cast<const float4*>(&Bs[buf][k][tx << 2]);
            #pragma unroll
            for (int i = 0; i < 8; i++) {
                float a = As[buf][(ty << 3) + i][k];
                acc[i][0] += a * b4.x;
                acc[i][1] += a * b4.y;
                acc[i][2] += a * b4.z;
                acc[i][3] += a * b4.w;
            }
        }
        __syncthreads();
    }

    #pragma unroll
    for (int i = 0; i < 8; i++) {
        int row = row0 + (ty << 3) + i;
        if (row < M) {
            float4 v = make_float4(acc[i][0], acc[i][1], acc[i][2], acc[i][3]);
            *reinterpret_cast<float4*>(C + (size_t)row * N + col0 + (tx << 2)) = v;
        }
    }
}

// ---------------- attention scores -----------------------------------------
__global__ void k_scores1(const float* __restrict__ att_src, const float* __restrict__ att_dst) {
    int n = blockIdx.x;
    int t = threadIdx.x;
    int h = t >> 5, lane = t & 31;
    const float* hp = g_h1 + (size_t)n * D1 + h * HID;
    float s1 = hp[lane] * att_src[h * HID + lane] + hp[lane + 32] * att_src[h * HID + lane + 32];
    float s2 = hp[lane] * att_dst[h * HID + lane] + hp[lane + 32] * att_dst[h * HID + lane + 32];
    #pragma unroll
    for (int o = 16; o; o >>= 1) {
        s1 += __shfl_down_sync(0xFFFFFFFF, s1, o);
        s2 += __shfl_down_sync(0xFFFFFFFF, s2, o);
    }
    if (lane == 0) {
        g_asrc1[n * HEADS + h] = s1;
        g_adst1[n * HEADS + h] = s2;
    }
}

__global__ void k_scores2(const float* __restrict__ att_src, const float* __restrict__ att_dst) {
    int w = threadIdx.x >> 5, lane = threadIdx.x & 31;
    int n = blockIdx.x * 8 + w;
    if (n >= NN) return;
    const float* hp = g_h2 + (size_t)n * HID;
    float s1 = hp[lane] * att_src[lane] + hp[lane + 32] * att_src[lane + 32];
    float s2 = hp[lane] * att_dst[lane] + hp[lane + 32] * att_dst[lane + 32];
    #pragma unroll
    for (int o = 16; o; o >>= 1) {
        s1 += __shfl_down_sync(0xFFFFFFFF, s1, o);
        s2 += __shfl_down_sync(0xFFFFFFFF, s2, o);
    }
    if (lane == 0) {
        g_asrc2[n] = s1;
        g_adst2[n] = s2;
    }
}

// ---------------- aggregation ----------------------------------------------
__device__ __forceinline__ float lrelu(float x) { return x > 0.f ? x : 0.2f * x; }

// layer 1: one node per 128-thread block; warp h handles head h; float2/lane
__global__ void k_agg1(const float* __restrict__ bias) {
    int n = blockIdx.x;
    int t = threadIdx.x;
    int h = t >> 5, lane = t & 31;
    int beg = g_rowptr[n], end = g_rowptr[n + 1];
    float ad = g_adst1[n * HEADS + h];
    float* esc = g_esc + (size_t)h * ETOT;

    // pass 1: warp-parallel online softmax stats; stash scores coalesced
    float m = -1e30f, d = 0.f;
    for (int e = beg + lane; e < end; e += 32) {
        int s = g_esrc[e];
        float x = lrelu(g_asrc1[s * HEADS + h] + ad);
        esc[e] = x;
        float mn = fmaxf(m, x);
        d = d * __expf(m - mn) + __expf(x - mn);
        m = mn;
    }
    #pragma unroll
    for (int o = 16; o; o >>= 1) {
        float mo = __shfl_xor_sync(0xFFFFFFFF, m, o);
        float dd = __shfl_xor_sync(0xFFFFFFFF, d, o);
        float mn = fmaxf(m, mo);
        d = d * __expf(m - mn) + dd * __expf(mo - mn);
        m = mn;
    }
    float inv = 1.f / (d + 1e-16f);
    __syncwarp();

    // pass 2: shuffle-broadcast weights, float2 gathers from L2-resident h1
    float2 acc = make_float2(0.f, 0.f);
    int c = lane << 1;
    const float* hrow = g_h1 + h * HID + c;
    for (int e0 = beg; e0 < end; e0 += 32) {
        int e = e0 + lane;
        int s = 0; float w = 0.f;
        if (e < end) {
            s = g_esrc[e];
            w = __expf(esc[e] - m) * inv;
        }
        int cnt = min(32, end - e0);
        for (int j = 0; j < cnt; j++) {
            int   sj = __shfl_sync(0xFFFFFFFF, s, j);
            float wj = __shfl_sync(0xFFFFFFFF, w, j);
            float2 v = *reinterpret_cast<const float2*>(hrow + (size_t)sj * D1);
            acc.x += v.x * wj;
            acc.y += v.y * wj;
        }
    }
    float v0 = acc.x + bias[h * HID + c];
    float v1 = acc.y + bias[h * HID + c + 1];
    g_buf1[(size_t)n * D1 + h * HID + c]     = v0 > 0.f ? v0 : __expf(v0) - 1.f;
    g_buf1[(size_t)n * D1 + h * HID + c + 1] = v1 > 0.f ? v1 : __expf(v1) - 1.f;
}

// layer 2: one node per warp (4 nodes per 128-thread block)
__global__ void k_agg2(const float* __restrict__ bias) {
    int w = threadIdx.x >> 5, lane = threadIdx.x & 31;
    int n = blockIdx.x * 4 + w;
    if (n >= NN) return;
    int beg = g_rowptr[n], end = g_rowptr[n + 1];
    float ad = g_adst2[n];

    float m = -1e30f, d = 0.f;
    for (int e = beg + lane; e < end; e += 32) {
        int s = g_esrc[e];
        float x = lrelu(g_asrc2[s] + ad);
        g_esc[e] = x;
        float mn = fmaxf(m, x);
        d = d * __expf(m - mn) + __expf(x - mn);
        m = mn;
    }
    #pragma unroll
    for (int o = 16; o; o >>= 1) {
        float mo = __shfl_xor_sync(0xFFFFFFFF, m, o);
        float dd = __shfl_xor_sync(0xFFFFFFFF, d, o);
        float mn = fmaxf(m, mo);
        d = d * __expf(m - mn) + dd * __expf(mo - mn);
        m = mn;
    }
    float inv = 1.f / (d + 1e-16f);
    __syncwarp();

    float2 acc = make_float2(0.f, 0.f);
    int c = lane << 1;
    for (int e0 = beg; e0 < end; e0 += 32) {
        int e = e0 + lane;
        int s = 0; float wt = 0.f;
        if (e < end) {
            s = g_esrc[e];
            wt = __expf(g_esc[e] - m) * inv;
        }
        int cnt = min(32, end - e0);
        for (int j = 0; j < cnt; j++) {
            int   sj = __shfl_sync(0xFFFFFFFF, s, j);
            float wj = __shfl_sync(0xFFFFFFFF, wt, j);
            float2 v = *reinterpret_cast<const float2*>(g_h2 + (size_t)sj * HID + c);
            acc.x += v.x * wj;
            acc.y += v.y * wj;
        }
    }
    float v0 = acc.x + bias[c];
    float v1 = acc.y + bias[c + 1];
    g_buf2[(size_t)n * HID + c]     = v0 > 0.f ? v0 : __expf(v0) - 1.f;
    g_buf2[(size_t)n * HID + c + 1] = v1 > 0.f ? v1 : __expf(v1) - 1.f;
}

// ---------------- fused MLP head: relu(h@Wm1+bm1)@Wm2+bm2 ------------------
__global__ void k_mlp(const float* __restrict__ Wm1, const float* __restrict__ bm1,
                      const float* __restrict__ Wm2, const float* __restrict__ bm2,
                      float* __restrict__ out) {
    __shared__ float sW1[HID * 32];
    __shared__ float sW2[32 * 2];
    __shared__ float sb1[32], sb2[2];
    __shared__ float hm[8][33];
    int t = threadIdx.x;
    for (int i = t; i < HID * 32; i += 256) sW1[i] = Wm1[i];
    if (t < 64) sW2[t] = Wm2[t];
    if (t < 32) sb1[t] = bm1[t];
    if (t < 2)  sb2[t] = bm2[t];
    __syncthreads();
    int nl = t >> 5, j = t & 31;
    int node = blockIdx.x * 8 + nl;
    if (node < NN) {
        const float* hrow = g_buf2 + (size_t)node * HID;
        float acc = sb1[j];
        #pragma unroll
        for (int k = 0; k < HID; k++) acc += hrow[k] * sW1[k * 32 + j];
        hm[nl][j] = fmaxf(acc, 0.f);
    }
    __syncthreads();
    if (node < NN && j < 2) {
        float acc = sb2[j];
        #pragma unroll
        for (int k = 0; k < 32; k++) acc += hm[nl][k] * sW2[k * 2 + j];
        out[node * 2 + j] = acc;
    }
}

// ---------------- launch ----------------------------------------------------
extern "C" void kernel_launch(void* const* d_in, const int* in_sizes, int n_in,
                              void* d_out, int out_size) {
    const float* x        = (const float*)d_in[0];
    const int*   eidx     = (const int*)d_in[1];
    const float* W1       = (const float*)d_in[2];
    const float* att_src1 = (const float*)d_in[3];
    const float* att_dst1 = (const float*)d_in[4];
    const float* b1       = (const float*)d_in[5];
    const float* W2       = (const float*)d_in[6];
    const float* att_src2 = (const float*)d_in[7];
    const float* att_dst2 = (const float*)d_in[8];
    const float* b2       = (const float*)d_in[9];
    const float* Wm1      = (const float*)d_in[10];
    const float* bm1      = (const float*)d_in[11];
    const float* Wm2      = (const float*)d_in[12];
    const float* bm2      = (const float*)d_in[13];
    float* out = (float*)d_out;

    int E = in_sizes[1] / 2;
    const int* srcp = eidx;
    const int* dstp = eidx + E;

    float *h1p, *buf1p, *h2p;
    cudaGetSymbolAddress((void**)&h1p,  g_h1);
    cudaGetSymbolAddress((void**)&buf1p, g_buf1);
    cudaGetSymbolAddress((void**)&h2p,  g_h2);

    // CSR build (dst-grouped, with self loops)
    k_zero_deg<<<(NN + 255) / 256, 256>>>();
    k_count<<<(E + 255) / 256, 256>>>(dstp, E);
    k_scan1<<<NBLK, 1024>>>();
    k_scan2<<<1, 32>>>();
    k_scan3<<<(NN + 255) / 256, 256>>>();
    k_scatter<<<(E + NN + 255) / 256, 256>>>(srcp, dstp, E);

    // layer 1
    k_gemm<<<dim3(D1 / 64, (NN + 127) / 128), 256>>>(x, W1, h1p, NN, D1, IN_CH);
    k_scores1<<<NN, 128>>>(att_src1, att_dst1);
    k_agg1<<<NN, 128>>>(b1);

    // layer 2
    k_gemm<<<dim3(HID / 64, (NN + 127) / 128), 256>>>(buf1p, W2, h2p, NN, HID, D1);
    k_scores2<<<(NN + 7) / 8, 256>>>(att_src2, att_dst2);
    k_agg2<<<(NN + 3) / 4, 128>>>(b2);

    // MLP head
    k_mlp<<<(NN + 7) / 8, 256>>>(Wm1, bm1, Wm2, bm2, out);
}

// round 3
// speedup vs baseline: 1.7374x; 1.0172x over previous
#include <cuda_runtime.h>
#include <cuda_bf16.h>
#include <cstdint>

#define NN 50000
#define EMAX 800000
#define ETOT (EMAX + NN)
#define IN_CH 128
#define HID 64
#define HEADS 4
#define D1 (HEADS * HID)   // 256
#define NBLK 49            // ceil(NN/1024)
#define KP1 (4 * IN_CH)    // 512  split-bf16 K for GEMM1
#define KP2 (4 * D1)       // 1024 split-bf16 K for GEMM2

// ---------------- scratch (static device globals; no runtime alloc) --------
__device__ __align__(128) float g_h1[NN * D1];     // layer1 GEMM out (fp32)
__device__ __align__(128) float g_h2[NN * HID];    // layer2 GEMM out (fp32)
__device__ __align__(128) float g_buf2[NN * HID];  // elu(agg2 + b2)
__device__ __align__(128) __nv_bfloat16 g_A1[(size_t)NN * KP1];   // packed x
__device__ __align__(128) __nv_bfloat16 g_A2[(size_t)NN * KP2];   // packed agg1 out
__device__ __align__(128) __nv_bfloat16 g_W1p[(size_t)KP1 * D1];
__device__ __align__(128) __nv_bfloat16 g_W2p[(size_t)KP2 * HID];
__device__ __align__(128) float g_asrc1[NN * HEADS];
__device__ __align__(128) float g_adst1[NN * HEADS];
__device__ __align__(128) float g_asrc2[NN];
__device__ __align__(128) float g_adst2[NN];
__device__ __align__(128) float g_esc[(size_t)HEADS * ETOT];
__device__ __align__(128) int   g_deg[NN];
__device__ __align__(128) int   g_rowptr[NN + 1];
__device__ __align__(128) int   g_cursor[NN];
__device__ __align__(128) int   g_esrc[ETOT];
__device__ __align__(128) int   g_part[64];

// ---------------- CSR build -------------------------------------------------
__global__ void k_zero_deg() {
    int i = blockIdx.x * blockDim.x + threadIdx.x;
    if (i < NN) g_deg[i] = 0;
}

__global__ void k_count(const int* __restrict__ dst, int E) {
    int i = blockIdx.x * blockDim.x + threadIdx.x;
    if (i < E) atomicAdd(&g_deg[dst[i]], 1);
}

__global__ void k_scan1() {
    __shared__ int ws[32];
    int t = threadIdx.x;
    int i = blockIdx.x * 1024 + t;
    int v = (i < NN) ? (g_deg[i] + 1) : 0;
    int x = v;
    #pragma unroll
    for (int o = 1; o < 32; o <<= 1) {
        int y = __shfl_up_sync(0xFFFFFFFF, x, o);
        if ((t & 31) >= o) x += y;
    }
    if ((t & 31) == 31) ws[t >> 5] = x;
    __syncthreads();
    if (t < 32) {
        int s = ws[t];
        #pragma unroll
        for (int o = 1; o < 32; o <<= 1) {
            int y = __shfl_up_sync(0xFFFFFFFF, s, o);
            if (t >= o) s += y;
        }
        ws[t] = s;
    }
    __syncthreads();
    int incl = x + ((t >= 32) ? ws[(t >> 5) - 1] : 0);
    if (i < NN) g_rowptr[i + 1] = incl;
    if (t == 1023) g_part[blockIdx.x] = incl;
}

__global__ void k_scan2() {
    int l = threadIdx.x;
    int a = (l < NBLK) ? g_part[l] : 0;
    int b = (l + 32 < NBLK) ? g_part[l + 32] : 0;
    int ia = a;
    #pragma unroll
    for (int o = 1; o < 32; o <<= 1) {
        int y = __shfl_up_sync(0xFFFFFFFF, ia, o);
        if (l >= o) ia += y;
    }
    int tot = __shfl_sync(0xFFFFFFFF, ia, 31);
    int ib = b;
    #pragma unroll
    for (int o = 1; o < 32; o <<= 1) {
        int y = __shfl_up_sync(0xFFFFFFFF, ib, o);
        if (l >= o) ib += y;
    }
    g_part[l] = ia - a;
    g_part[l + 32] = tot + ib - b;
}

__global__ void k_scan3() {
    int i = blockIdx.x * blockDim.x + threadIdx.x;
    if (i >= NN) return;
    int off = g_part[i >> 10];
    int rp = g_rowptr[i + 1] + off;
    g_rowptr[i + 1] = rp;
    g_cursor[i] = rp - (g_deg[i] + 1);
    if (i == 0) g_rowptr[0] = 0;
}

__global__ void k_scatter(const int* __restrict__ src, const int* __restrict__ dst, int E) {
    int i = blockIdx.x * blockDim.x + threadIdx.x;
    if (i < E) {
        int p = atomicAdd(&g_cursor[dst[i]], 1);
        g_esrc[p] = src[i];
    } else if (i < E + NN) {
        int n = i - E;
        int p = atomicAdd(&g_cursor[n], 1);
        g_esrc[p] = n;
    }
}

// ---------------- split-bf16 packing ---------------------------------------
__device__ __forceinline__ void split_bf16(float f, __nv_bfloat16& hi, __nv_bfloat16& lo) {
    hi = __float2bfloat16(f);
    lo = __float2bfloat16(f - __bfloat162float(hi));
}

// A pattern per source element k: [hi, hi, lo, lo] at 4k..4k+3
__global__ void k_packA1(const float* __restrict__ x) {
    int i = blockIdx.x * blockDim.x + threadIdx.x;
    if (i >= NN * IN_CH) return;
    int m = i >> 7, k = i & (IN_CH - 1);
    __nv_bfloat16 hi, lo;
    split_bf16(x[i], hi, lo);
    __nv_bfloat162* p = reinterpret_cast<__nv_bfloat162*>(g_A1 + (size_t)m * KP1 + 4 * k);
    p[0] = __halves2bfloat162(hi, hi);
    p[1] = __halves2bfloat162(lo, lo);
}

// B pattern per source element k: [hi, lo, hi, lo] at rows 4k..4k+3
__global__ void k_packW(const float* __restrict__ W, __nv_bfloat16* __restrict__ dst,
                        int K, int N) {
    int i = blockIdx.x * blockDim.x + threadIdx.x;
    if (i >= K * N) return;
    int k = i / N, n = i - k * N;
    __nv_bfloat16 hi, lo;
    split_bf16(W[i], hi, lo);
    size_t base = (size_t)(4 * k) * N + n;
    dst[base]         = hi;
    dst[base + N]     = lo;
    dst[base + 2 * N] = hi;
    dst[base + 3 * N] = lo;
}

// ---------------- bf16 tensor-core GEMM ------------------------------------
// C[M,N] = A[M,Kp] @ B[Kp,N], bf16 in / fp32 out. BM=128 BN=64 BK=64.
__device__ __forceinline__ void cp16(uint32_t dst, const void* src, int sz) {
    asm volatile("cp.async.ca.shared.global [%0], [%1], 16, %2;\n"
                 :: "r"(dst), "l"(src), "r"(sz));
}
__device__ __forceinline__ void ldsm4(uint32_t* r, uint32_t a) {
    asm volatile("ldmatrix.sync.aligned.m8n8.x4.shared.b16 {%0,%1,%2,%3}, [%4];"
                 : "=r"(r[0]), "=r"(r[1]), "=r"(r[2]), "=r"(r[3]) : "r"(a));
}
__device__ __forceinline__ void ldsm4t(uint32_t* r, uint32_t a) {
    asm volatile("ldmatrix.sync.aligned.m8n8.x4.trans.shared.b16 {%0,%1,%2,%3}, [%4];"
                 : "=r"(r[0]), "=r"(r[1]), "=r"(r[2]), "=r"(r[3]) : "r"(a));
}
__device__ __forceinline__ void mma16816(float* c, const uint32_t* a, uint32_t b0, uint32_t b1) {
    asm volatile("mma.sync.aligned.m16n8k16.row.col.f32.bf16.bf16.f32 "
                 "{%0,%1,%2,%3}, {%4,%5,%6,%7}, {%8,%9}, {%0,%1,%2,%3};"
                 : "+f"(c[0]), "+f"(c[1]), "+f"(c[2]), "+f"(c[3])
                 : "r"(a[0]), "r"(a[1]), "r"(a[2]), "r"(a[3]), "r"(b0), "r"(b1));
}
__device__ __forceinline__ uint32_t sw128(uint32_t off) {
    return off ^ ((off >> 3) & 0x70);
}

__global__ __launch_bounds__(256) void k_gemm_bf16(
        const __nv_bfloat16* __restrict__ A, const __nv_bfloat16* __restrict__ B,
        float* __restrict__ C, int M, int N, int Kp) {
    __shared__ __align__(1024) char smem_raw[49152];  // A: 2x16KB, B: 2x8KB
    uint32_t sA = (uint32_t)__cvta_generic_to_shared(smem_raw);
    uint32_t sB = sA + 32768;
    int t = threadIdx.x;
    int warp = t >> 5, lane = t & 31;
    int wm = warp & 3, wn = warp >> 2;
    int row0 = blockIdx.y * 128, col0 = blockIdx.x * 64;

    float acc[2][4][4];
    #pragma unroll
    for (int mt = 0; mt < 2; mt++)
        #pragma unroll
        for (int nt = 0; nt < 4; nt++)
            #pragma unroll
            for (int r = 0; r < 4; r++) acc[mt][nt][r] = 0.f;

    int nIter = Kp >> 6;

    auto load_tiles = [&](int it, int buf) {
        int k0 = it << 6;
        #pragma unroll
        for (int i = 0; i < 4; i++) {            // A: 128 rows x 8 chunks
            int id = t + i * 256;
            int r = id >> 3, kc = id & 7;
            uint32_t off = sw128(r * 128 + kc * 16);
            int sz = (row0 + r < M) ? 16 : 0;
            cp16(sA + buf * 16384 + off, A + (size_t)(row0 + r) * Kp + k0 + kc * 8, sz);
        }
        #pragma unroll
        for (int i = 0; i < 2; i++) {            // B: 64 rows x 8 chunks
            int id = t + i * 256;
            int r = id >> 3, kc = id & 7;
            uint32_t off = sw128(r * 128 + kc * 16);
            cp16(sB + buf * 8192 + off, B + (size_t)(k0 + r) * N + col0 + kc * 8, 16);
        }
        asm volatile("cp.async.commit_group;\n" ::: "memory");
    };

    load_tiles(0, 0);
    for (int it = 0; it < nIter; it++) {
        int buf = it & 1;
        if (it + 1 < nIter) {
            load_tiles(it + 1, buf ^ 1);
            asm volatile("cp.async.wait_group 1;\n" ::: "memory");
        } else {
            asm volatile("cp.async.wait_group 0;\n" ::: "memory");
        }
        __syncthreads();
        uint32_t aBuf = sA + buf * 16384;
        uint32_t bBuf = sB + buf * 8192;
        #pragma unroll
        for (int kk = 0; kk < 4; kk++) {
            int k0 = kk << 4;
            uint32_t afr[2][4], bfr[2][4];
            #pragma unroll
            for (int mt = 0; mt < 2; mt++) {
                int r = wm * 32 + mt * 16 + (lane & 15);
                uint32_t off = sw128(r * 128 + (k0 + (lane >> 4) * 8) * 2);
                ldsm4(afr[mt], aBuf + off);
            }
            #pragma unroll
            for (int np = 0; np < 2; np++) {
                int k = k0 + (lane & 7) + ((lane >> 3) & 1) * 8;
                int n = wn * 32 + np * 16 + (lane >> 4) * 8;
                uint32_t off = sw128(k * 128 + n * 2);
                ldsm4t(bfr[np], bBuf + off);
            }
            #pragma unroll
            for (int mt = 0; mt < 2; mt++)
                #pragma unroll
                for (int nt = 0; nt < 4; nt++)
                    mma16816(acc[mt][nt], afr[mt],
                             bfr[nt >> 1][(nt & 1) * 2], bfr[nt >> 1][(nt & 1) * 2 + 1]);
        }
        __syncthreads();
    }

    #pragma unroll
    for (int mt = 0; mt < 2; mt++)
        #pragma unroll
        for (int nt = 0; nt < 4; nt++) {
            int r = row0 + wm * 32 + mt * 16 + (lane >> 2);
            int cn = col0 + wn * 32 + nt * 8 + (lane & 3) * 2;
            if (r < M) {
                C[(size_t)r * N + cn]     = acc[mt][nt][0];
                C[(size_t)r * N + cn + 1] = acc[mt][nt][1];
            }
            if (r + 8 < M) {
                C[(size_t)(r + 8) * N + cn]     = acc[mt][nt][2];
                C[(size_t)(r + 8) * N + cn + 1] = acc[mt][nt][3];
            }
        }
}

// ---------------- attention scores -----------------------------------------
__global__ void k_scores1(const float* __restrict__ att_src, const float* __restrict__ att_dst) {
    int n = blockIdx.x;
    int t = threadIdx.x;
    int h = t >> 5, lane = t & 31;
    const float* hp = g_h1 + (size_t)n * D1 + h * HID;
    float s1 = hp[lane] * att_src[h * HID + lane] + hp[lane + 32] * att_src[h * HID + lane + 32];
    float s2 = hp[lane] * att_dst[h * HID + lane] + hp[lane + 32] * att_dst[h * HID + lane + 32];
    #pragma unroll
    for (int o = 16; o; o >>= 1) {
        s1 += __shfl_down_sync(0xFFFFFFFF, s1, o);
        s2 += __shfl_down_sync(0xFFFFFFFF, s2, o);
    }
    if (lane == 0) {
        g_asrc1[n * HEADS + h] = s1;
        g_adst1[n * HEADS + h] = s2;
    }
}

__global__ void k_scores2(const float* __restrict__ att_src, const float* __restrict__ att_dst) {
    int w = threadIdx.x >> 5, lane = threadIdx.x & 31;
    int n = blockIdx.x * 8 + w;
    if (n >= NN) return;
    const float* hp = g_h2 + (size_t)n * HID;
    float s1 = hp[lane] * att_src[lane] + hp[lane + 32] * att_src[lane + 32];
    float s2 = hp[lane] * att_dst[lane] + hp[lane + 32] * att_dst[lane + 32];
    #pragma unroll
    for (int o = 16; o; o >>= 1) {
        s1 += __shfl_down_sync(0xFFFFFFFF, s1, o);
        s2 += __shfl_down_sync(0xFFFFFFFF, s2, o);
    }
    if (lane == 0) {
        g_asrc2[n] = s1;
        g_adst2[n] = s2;
    }
}

// ---------------- aggregation ----------------------------------------------
__device__ __forceinline__ float lrelu(float x) { return x > 0.f ? x : 0.2f * x; }

// layer 1: one node per 128-thread block; warp h = head h; epilogue packs A2
__global__ void k_agg1(const float* __restrict__ bias) {
    int n = blockIdx.x;
    int t = threadIdx.x;
    int h = t >> 5, lane = t & 31;
    int beg = g_rowptr[n], end = g_rowptr[n + 1];
    float ad = g_adst1[n * HEADS + h];
    float* esc = g_esc + (size_t)h * ETOT;

    float m = -1e30f, d = 0.f;
    for (int e = beg + lane; e < end; e += 32) {
        int s = g_esrc[e];
        float x = lrelu(g_asrc1[s * HEADS + h] + ad);
        esc[e] = x;
        float mn = fmaxf(m, x);
        d = d * __expf(m - mn) + __expf(x - mn);
        m = mn;
    }
    #pragma unroll
    for (int o = 16; o; o >>= 1) {
        float mo = __shfl_xor_sync(0xFFFFFFFF, m, o);
        float dd = __shfl_xor_sync(0xFFFFFFFF, d, o);
        float mn = fmaxf(m, mo);
        d = d * __expf(m - mn) + dd * __expf(mo - mn);
        m = mn;
    }
    float inv = 1.f / (d + 1e-16f);
    __syncwarp();

    float2 acc = make_float2(0.f, 0.f);
    int c = lane << 1;
    const float* hrow = g_h1 + h * HID + c;
    for (int e0 = beg; e0 < end; e0 += 32) {
        int e = e0 + lane;
        int s = 0; float w = 0.f;
        if (e < end) {
            s = g_esrc[e];
            w = __expf(esc[e] - m) * inv;
        }
        int cnt = min(32, end - e0);
        for (int j = 0; j < cnt; j++) {
            int   sj = __shfl_sync(0xFFFFFFFF, s, j);
            float wj = __shfl_sync(0xFFFFFFFF, w, j);
            float2 v = *reinterpret_cast<const float2*>(hrow + (size_t)sj * D1);
            acc.x += v.x * wj;
            acc.y += v.y * wj;
        }
    }
    int j0 = h * HID + c;
    float v0 = acc.x + bias[j0];
    float v1 = acc.y + bias[j0 + 1];
    v0 = v0 > 0.f ? v0 : __expf(v0) - 1.f;   // elu
    v1 = v1 > 0.f ? v1 : __expf(v1) - 1.f;
    __nv_bfloat16 h0, l0, h1, l1;
    split_bf16(v0, h0, l0);
    split_bf16(v1, h1, l1);
    __nv_bfloat162* p = reinterpret_cast<__nv_bfloat162*>(g_A2 + (size_t)n * KP2 + 4 * j0);
    p[0] = __halves2bfloat162(h0, h0);
    p[1] = __halves2bfloat162(l0, l0);
    p[2] = __halves2bfloat162(h1, h1);
    p[3] = __halves2bfloat162(l1, l1);
}

// layer 2: one node per warp
__global__ void k_agg2(const float* __restrict__ bias) {
    int w = threadIdx.x >> 5, lane = threadIdx.x & 31;
    int n = blockIdx.x * 4 + w;
    if (n >= NN) return;
    int beg = g_rowptr[n], end = g_rowptr[n + 1];
    float ad = g_adst2[n];

    float m = -1e30f, d = 0.f;
    for (int e = beg + lane; e < end; e += 32) {
        int s = g_esrc[e];
        float x = lrelu(g_asrc2[s] + ad);
        g_esc[e] = x;
        float mn = fmaxf(m, x);
        d = d * __expf(m - mn) + __expf(x - mn);
        m = mn;
    }
    #pragma unroll
    for (int o = 16; o; o >>= 1) {
        float mo = __shfl_xor_sync(0xFFFFFFFF, m, o);
        float dd = __shfl_xor_sync(0xFFFFFFFF, d, o);
        float mn = fmaxf(m, mo);
        d = d * __expf(m - mn) + dd * __expf(mo - mn);
        m = mn;
    }
    float inv = 1.f / (d + 1e-16f);
    __syncwarp();

    float2 acc = make_float2(0.f, 0.f);
    int c = lane << 1;
    for (int e0 = beg; e0 < end; e0 += 32) {
        int e = e0 + lane;
        int s = 0; float wt = 0.f;
        if (e < end) {
            s = g_esrc[e];
            wt = __expf(g_esc[e] - m) * inv;
        }
        int cnt = min(32, end - e0);
        for (int j = 0; j < cnt; j++) {
            int   sj = __shfl_sync(0xFFFFFFFF, s, j);
            float wj = __shfl_sync(0xFFFFFFFF, wt, j);
            float2 v = *reinterpret_cast<const float2*>(g_h2 + (size_t)sj * HID + c);
            acc.x += v.x * wj;
            acc.y += v.y * wj;
        }
    }
    float v0 = acc.x + bias[c];
    float v1 = acc.y + bias[c + 1];
    g_buf2[(size_t)n * HID + c]     = v0 > 0.f ? v0 : __expf(v0) - 1.f;
    g_buf2[(size_t)n * HID + c + 1] = v1 > 0.f ? v1 : __expf(v1) - 1.f;
}

// ---------------- fused MLP head -------------------------------------------
__global__ void k_mlp(const float* __restrict__ Wm1, const float* __restrict__ bm1,
                      const float* __restrict__ Wm2, const float* __restrict__ bm2,
                      float* __restrict__ out) {
    __shared__ float sW1[HID * 32];
    __shared__ float sW2[32 * 2];
    __shared__ float sb1[32], sb2[2];
    __shared__ float hm[8][33];
    int t = threadIdx.x;
    for (int i = t; i < HID * 32; i += 256) sW1[i] = Wm1[i];
    if (t < 64) sW2[t] = Wm2[t];
    if (t < 32) sb1[t] = bm1[t];
    if (t < 2)  sb2[t] = bm2[t];
    __syncthreads();
    int nl = t >> 5, j = t & 31;
    int node = blockIdx.x * 8 + nl;
    if (node < NN) {
        const float* hrow = g_buf2 + (size_t)node * HID;
        float acc = sb1[j];
        #pragma unroll
        for (int k = 0; k < HID; k++) acc += hrow[k] * sW1[k * 32 + j];
        hm[nl][j] = fmaxf(acc, 0.f);
    }
    __syncthreads();
    if (node < NN && j < 2) {
        float acc = sb2[j];
        #pragma unroll
        for (int k = 0; k < 32; k++) acc += hm[nl][k] * sW2[k * 2 + j];
        out[node * 2 + j] = acc;
    }
}

// ---------------- launch ----------------------------------------------------
extern "C" void kernel_launch(void* const* d_in, const int* in_sizes, int n_in,
                              void* d_out, int out_size) {
    const float* x        = (const float*)d_in[0];
    const int*   eidx     = (const int*)d_in[1];
    const float* W1       = (const float*)d_in[2];
    const float* att_src1 = (const float*)d_in[3];
    const float* att_dst1 = (const float*)d_in[4];
    const float* b1       = (const float*)d_in[5];
    const float* W2       = (const float*)d_in[6];
    const float* att_src2 = (const float*)d_in[7];
    const float* att_dst2 = (const float*)d_in[8];
    const float* b2       = (const float*)d_in[9];
    const float* Wm1      = (const float*)d_in[10];
    const float* bm1      = (const float*)d_in[11];
    const float* Wm2      = (const float*)d_in[12];
    const float* bm2      = (const float*)d_in[13];
    float* out = (float*)d_out;

    int E = in_sizes[1] / 2;
    const int* srcp = eidx;
    const int* dstp = eidx + E;

    float *h1p, *h2p;
    __nv_bfloat16 *a1p, *a2p, *w1p, *w2p;
    cudaGetSymbolAddress((void**)&h1p, g_h1);
    cudaGetSymbolAddress((void**)&h2p, g_h2);
    cudaGetSymbolAddress((void**)&a1p, g_A1);
    cudaGetSymbolAddress((void**)&a2p, g_A2);
    cudaGetSymbolAddress((void**)&w1p, g_W1p);
    cudaGetSymbolAddress((void**)&w2p, g_W2p);

    // split-bf16 packing (inputs + weights)
    k_packA1<<<(NN * IN_CH + 255) / 256, 256>>>(x);
    k_packW<<<(IN_CH * D1 + 255) / 256, 256>>>(W1, w1p, IN_CH, D1);
    k_packW<<<(D1 * HID + 255) / 256, 256>>>(W2, w2p, D1, HID);

    // layer 1 GEMM (tensor cores, split-bf16 exact fp32)
    k_gemm_bf16<<<dim3(D1 / 64, (NN + 127) / 128), 256>>>(a1p, w1p, h1p, NN, D1, KP1);

    // CSR build (dst-grouped, with self loops)
    k_zero_deg<<<(NN + 255) / 256, 256>>>();
    k_count<<<(E + 255) / 256, 256>>>(dstp, E);
    k_scan1<<<NBLK, 1024>>>();
    k_scan2<<<1, 32>>>();
    k_scan3<<<(NN + 255) / 256, 256>>>();
    k_scatter<<<(E + NN + 255) / 256, 256>>>(srcp, dstp, E);

    // layer 1 attention + aggregation (packs A2 in epilogue)
    k_scores1<<<NN, 128>>>(att_src1, att_dst1);
    k_agg1<<<NN, 128>>>(b1);

    // layer 2
    k_gemm_bf16<<<dim3(HID / 64, (NN + 127) / 128), 256>>>(a2p, w2p, h2p, NN, HID, KP2);
    k_scores2<<<(NN + 7) / 8, 256>>>(att_src2, att_dst2);
    k_agg2<<<(NN + 3) / 4, 128>>>(b2);

    // MLP head
    k_mlp<<<(NN + 7) / 8, 256>>>(Wm1, bm1, Wm2, bm2, out);
}